// round 15
// baseline (speedup 1.0000x reference)
#include <cuda_runtime.h>
#include <math.h>
#include <stdint.h>

#define B 4
#define N 64
#define T 256
#define H 256
#define L 5
#define TOPK 8
#define BT (B*T)

#define RB8 8           // rows per block in GEMM kernels
#define XP 12           // transposed-activation row stride (16B-aligned)
#define RP 9            // reduction buffer stride (conflict-free)

// k_dots tiling
#define TB 64           // t-tile
#define NG 4            // peers per block

__constant__ int c_lags[L] = {1, 5, 10, 21, 30};

// -------- scratch (device globals: no allocation allowed) --------
__device__ float g_W[H*H];      // wq^T @ wk
__device__ float g_btil[H];     // bq @ wk
__device__ float g_v[H];        // wq^T @ bk
__device__ float g_c0;          // bq . bk
__device__ float g_wvT[H*H];
__device__ float g_w1T[H*H];
__device__ float g_w2T[H*H];
__device__ float g_Qt[BT*H];    // Q tilde
__device__ float g_c[BT];       // Q . bk per row
__device__ float g_lg[BT*N*L];  // full logits
__device__ float g_agg[BT*H];   // weighted sum of selected peer rows
__device__ float g_sw[BT];      // sum of weights

// ---- packed f32x2 helpers ----
__device__ __forceinline__ uint64_t pack2(float lo, float hi) {
    uint64_t r;
    asm("mov.b64 %0, {%1, %2};" : "=l"(r) : "f"(lo), "f"(hi));
    return r;
}
__device__ __forceinline__ void unpack2(uint64_t v, float& lo, float& hi) {
    asm("mov.b64 {%0, %1}, %2;" : "=f"(lo), "=f"(hi) : "l"(v));
}
__device__ __forceinline__ void ffma2(uint64_t& d, uint64_t a, uint64_t b) {
    asm("fma.rn.f32x2 %0, %1, %2, %0;" : "+l"(d) : "l"(a), "l"(b));
}

// ---- GEMM core: 8 rows, 128-long k-range starting at k0 (R14, measured).
__device__ __forceinline__ void gemm8k(const float* __restrict__ Wg,
                                       const float* __restrict__ XT,
                                       uint64_t* acc, int j, int k0) {
    float wb[2][8];
    #pragma unroll
    for (int p = 0; p < 2; p++)
        #pragma unroll
        for (int hh = 0; hh < 8; hh++) wb[p][hh] = Wg[(k0 + p*8 + hh)*H + j];

    ulonglong2 xs[2][2];
    {
        const ulonglong2* xp = (const ulonglong2*)(XT + (size_t)k0*XP);
        xs[0][0] = xp[0]; xs[0][1] = xp[1];
    }
    #pragma unroll 2
    for (int kt = 0; kt < 16; kt++) {
        int curb = kt & 1;
        float w[8];
        #pragma unroll
        for (int hh = 0; hh < 8; hh++) w[hh] = wb[curb][hh];
        if (kt + 2 < 16) {
            #pragma unroll
            for (int hh = 0; hh < 8; hh++)
                wb[curb][hh] = Wg[(k0 + (kt+2)*8 + hh)*H + j];
        }
        #pragma unroll
        for (int hh = 0; hh < 8; hh++) {
            int hrel = kt*8 + hh;
            int cur = hrel & 1, nxt = cur ^ 1;
            int hnrel = (hrel + 1) & 127;
            const ulonglong2* xp = (const ulonglong2*)(XT + (size_t)(k0 + hnrel)*XP);
            xs[nxt][0] = xp[0];
            xs[nxt][1] = xp[1];
            uint64_t w2 = pack2(w[hh], w[hh]);
            ffma2(acc[0], xs[cur][0].x, w2); ffma2(acc[1], xs[cur][0].y, w2);
            ffma2(acc[2], xs[cur][1].x, w2); ffma2(acc[3], xs[cur][1].y, w2);
        }
    }
}

// =============== prep: W = wq^T wk, biases folded, transposes ===============
__global__ void k_prep(const float* __restrict__ wq, const float* __restrict__ wk,
                       const float* __restrict__ bq, const float* __restrict__ bk,
                       const float* __restrict__ wv, const float* __restrict__ w1,
                       const float* __restrict__ w2) {
    int bidx = blockIdx.x;
    int j = threadIdx.x;
    if (bidx < H) {
        int h = bidx;
        __shared__ float s_wq[H];
        s_wq[j] = wq[j*H + h];
        __syncthreads();
        float acc = 0.f;
        #pragma unroll 4
        for (int m = 0; m < H; m++) acc += s_wq[m] * wk[m*H + j];
        g_W[h*H + j]   = acc;
        g_wvT[h*H + j] = wv[j*H + h];
        g_w1T[h*H + j] = w1[j*H + h];
        g_w2T[h*H + j] = w2[j*H + h];
    } else if (bidx == H) {
        float acc = 0.f;
        for (int m = 0; m < H; m++) acc += bq[m] * wk[m*H + j];
        g_btil[j] = acc;
    } else if (bidx == H + 1) {
        float acc = 0.f;
        for (int m = 0; m < H; m++) acc += wq[m*H + j] * bk[m];
        g_v[j] = acc;
    } else {
        if (j < 32) {
            float s = 0.f;
            for (int i = j; i < H; i += 32) s += bq[i] * bk[i];
            for (int off = 16; off; off >>= 1) s += __shfl_down_sync(0xffffffffu, s, off);
            if (j == 0) g_c0 = s;
        }
    }
}

// ========= Qtilde = target_h @ W + btil ; c = target_h . v + c0 (R14) =======
__global__ void __launch_bounds__(512) k_qtilde(const float* __restrict__ x) {
    __shared__ __align__(16) float s_x[H*XP];
    __shared__ float s_red[H*RP];
    __shared__ float s_part[16][4];
    int r0 = blockIdx.x * RB8;
    int tid = threadIdx.x;
    int j = tid & 255;
    int kh = tid >> 8;
    int k0 = kh << 7;
    int wid = tid >> 5, lane = tid & 31;

    float v4[4];
    #pragma unroll
    for (int r = 0; r < 4; r++) v4[r] = x[(r0 + kh*4 + r)*H + j];
    *(float4*)&s_x[j*XP + kh*4] = make_float4(v4[0], v4[1], v4[2], v4[3]);

    float gv = g_v[j];
    #pragma unroll
    for (int r = 0; r < 4; r++) {
        float s = v4[r] * gv;
        for (int off = 16; off; off >>= 1) s += __shfl_down_sync(0xffffffffu, s, off);
        if (lane == 0) s_part[wid][r] = s;
    }
    __syncthreads();
    if (tid < RB8) {
        int src = tid >> 2, rs = tid & 3;
        float s = g_c0;
        #pragma unroll
        for (int w = 0; w < 8; w++) s += s_part[src*8 + w][rs];
        g_c[r0 + tid] = s;
    }

    uint64_t acc[4];
    float bt = (kh == 0) ? g_btil[j] : 0.f;
    #pragma unroll
    for (int i = 0; i < 4; i++) acc[i] = pack2(bt, bt);
    gemm8k(g_W, s_x, acc, j, k0);

    if (kh) {
        #pragma unroll
        for (int i = 0; i < 4; i++) {
            float lo, hi; unpack2(acc[i], lo, hi);
            s_red[j*RP + 2*i] = lo; s_red[j*RP + 2*i + 1] = hi;
        }
    }
    __syncthreads();
    if (!kh) {
        #pragma unroll
        for (int i = 0; i < 4; i++) {
            float lo, hi; unpack2(acc[i], lo, hi);
            g_Qt[(r0 + 2*i    )*H + j] = lo + s_red[j*RP + 2*i];
            g_Qt[(r0 + 2*i + 1)*H + j] = hi + s_red[j*RP + 2*i + 1];
        }
    }
}

// ===== k_dots: logits for (b, 64-t tile, 4-peer group). Each peer row loaded
// ONCE, dotted against up to 5 staged Q rows (lag diagonal reuse). Row
// prefetch issued before the shfl-reduction chains.
__global__ void k_dots(const float* __restrict__ peer,
                       const int* __restrict__ mask) {
    extern __shared__ float sm[];
    float* s_q  = sm;                   // [TB][H] = 65536 B
    float* s_lg = sm + TB*H;            // [TB][NG][L]
    float* s_c  = s_lg + TB*NG*L;       // [TB]
    int*   s_mi = (int*)(s_c + TB);     // [NG]

    int bid = blockIdx.x;
    int ng = bid & 15;                  // 16 n-groups of 4
    int tt = (bid >> 4) & 3;            // 4 t-tiles of 64
    int b  = bid >> 6;
    int t0 = tt * TB;
    int n0 = ng * NG;
    int tid = threadIdx.x;              // 256
    int wid = tid >> 5, lane = tid & 31;

    {
        const float4* src = (const float4*)&g_Qt[(b*T + t0)*H];
        float4* dst = (float4*)s_q;
        for (int i = tid; i < TB*H/4; i += 256) dst[i] = src[i];
        for (int i = tid; i < TB*NG*L; i += 256) s_lg[i] = -INFINITY;
        if (tid < TB) s_c[tid] = g_c[b*T + t0 + tid];
        if (tid < NG) s_mi[tid] = mask[b*N + n0 + tid];
    }
    __syncthreads();

    int tp_lo = t0 - 30; if (tp_lo < 0) tp_lo = 0;
    int tp_hi = t0 + TB - 2;

    for (int nl = 0; nl < NG; nl++) {
        if (!s_mi[nl]) continue;
        const float4* base = (const float4*)(peer + ((size_t)((b*N + n0 + nl)*T)) * H);
        int tp = tp_lo + wid;
        if (tp > tp_hi) continue;
        float4 c0 = base[tp*64 + lane];
        float4 c1 = base[tp*64 + 32 + lane];
        while (tp <= tp_hi) {
            int tpn = tp + 8;
            float4 p0, p1;
            if (tpn <= tp_hi) {         // prefetch next row before the shfl chain
                p0 = base[tpn*64 + lane];
                p1 = base[tpn*64 + 32 + lane];
            }
            float s[L]; int tl[L];
            #pragma unroll
            for (int l = 0; l < L; l++) {
                tl[l] = tp + c_lags[l] - t0;
                s[l] = 0.f;
                if ((unsigned)tl[l] < TB) {
                    const float4* q4 = (const float4*)&s_q[tl[l]*H];
                    float4 q0 = q4[lane];
                    float4 q1 = q4[lane + 32];
                    s[l] = c0.x*q0.x + c0.y*q0.y + c0.z*q0.z + c0.w*q0.w
                         + c1.x*q1.x + c1.y*q1.y + c1.z*q1.z + c1.w*q1.w;
                }
            }
            #pragma unroll
            for (int off = 16; off; off >>= 1) {
                #pragma unroll
                for (int l = 0; l < L; l++)
                    s[l] += __shfl_down_sync(0xffffffffu, s[l], off);
            }
            if (lane == 0) {
                #pragma unroll
                for (int l = 0; l < L; l++)
                    if ((unsigned)tl[l] < TB)
                        s_lg[(tl[l]*NG + nl)*L + l] = (s[l] + s_c[tl[l]]) * 0.0625f;
            }
            tp = tpn; c0 = p0; c1 = p1;
        }
    }
    __syncthreads();

    // flush: g_lg[(b*T+t)*(N*L) + n0*L + (nl*L+l)]
    for (int i = tid; i < TB*NG*L; i += 256) {
        int trow = i / (NG*L);
        int rem = i - trow*(NG*L);
        g_lg[(size_t)(b*T + t0 + trow)*(N*L) + n0*L + rem] = s_lg[i];
    }
}

// ===== k_topk (R7, measured 11.0us): top-8 over 320, softmax, aggregate =====
__global__ void k_topk(const float* __restrict__ peer) {
    __shared__ float s_l[N*L];
    __shared__ float swt[TOPK];
    __shared__ int   sidx[TOPK];
    int bt = blockIdx.x;
    int b = bt >> 8;
    int t = bt & 255;
    int tid = threadIdx.x;          // 128 threads
    int wid = tid >> 5, lane = tid & 31;

    for (int i = tid; i < N*L; i += 128) s_l[i] = g_lg[(size_t)bt*(N*L) + i];
    __syncthreads();

    if (wid == 0) {
        float vals[TOPK];
        for (int k = 0; k < TOPK; k++) {
            float bv = -INFINITY; int bi = 0x7fffffff;
            for (int i = lane; i < N*L; i += 32) {
                float v = s_l[i];
                if (v > bv || (v == bv && i < bi)) { bv = v; bi = i; }
            }
            for (int off = 16; off; off >>= 1) {
                float ov = __shfl_down_sync(0xffffffffu, bv, off);
                int   oi = __shfl_down_sync(0xffffffffu, bi, off);
                if (ov > bv || (ov == bv && oi < bi)) { bv = ov; bi = oi; }
            }
            bi = __shfl_sync(0xffffffffu, bi, 0);
            bv = __shfl_sync(0xffffffffu, bv, 0);
            if (lane == 0) { sidx[k] = bi; vals[k] = bv; s_l[bi] = -INFINITY; }
            __syncwarp();
        }
        if (lane == 0) {
            float m = -INFINITY;
            bool allinf = true;
            float safe[TOPK];
            #pragma unroll
            for (int k = 0; k < TOPK; k++) {
                bool ii = isinf(vals[k]);
                allinf = allinf && ii;
                safe[k] = ii ? -1e9f : vals[k];
                if (safe[k] > m) m = safe[k];
            }
            float sw_ = 0.f;
            if (allinf) {
                #pragma unroll
                for (int k = 0; k < TOPK; k++) swt[k] = 0.f;
            } else {
                float e[TOPK]; float tot = 0.f;
                #pragma unroll
                for (int k = 0; k < TOPK; k++) { e[k] = expf(safe[k] - m); tot += e[k]; }
                #pragma unroll
                for (int k = 0; k < TOPK; k++) { float w = e[k] / tot; swt[k] = w; sw_ += w; }
            }
            g_sw[bt] = sw_;
        }
    }
    __syncthreads();

    float acc0 = 0.f, acc1 = 0.f;
    #pragma unroll
    for (int k = 0; k < TOPK; k++) {
        float w = swt[k];
        if (w != 0.f) {
            int d = sidx[k];
            int n = d / L, l = d - n*L;
            int tp = t - c_lags[l];
            const float* row = peer + ((size_t)((b*N + n)*T + tp)) * H;
            acc0 += w * row[tid];
            acc1 += w * row[tid + 128];
        }
    }
    g_agg[bt*H + tid]       = acc0;
    g_agg[bt*H + tid + 128] = acc1;
}

// ===== cs_y = agg@wv^T + sw*bv ; FFN(elu) ; residual ; LayerNorm (R14) ======
__global__ void __launch_bounds__(512) k_ffn(
                      const float* __restrict__ bv, const float* __restrict__ b1,
                      const float* __restrict__ b2, const float* __restrict__ gamma,
                      const float* __restrict__ beta, float* __restrict__ out) {
    __shared__ __align__(16) float s_x[H*XP];
    __shared__ float s_red[H*RP];
    __shared__ float s_sw[RB8];
    __shared__ float s_mu[RB8], s_rs[RB8];

    int r0 = blockIdx.x * RB8;
    int tid = threadIdx.x;
    int j = tid & 255;
    int kh = tid >> 8;
    int k0 = kh << 7;
    int wid = tid >> 5, lane = tid & 31;

    {
        float v4[4];
        #pragma unroll
        for (int r = 0; r < 4; r++) v4[r] = g_agg[(r0 + kh*4 + r)*H + j];
        *(float4*)&s_x[j*XP + kh*4] = make_float4(v4[0], v4[1], v4[2], v4[3]);
    }
    if (tid < RB8) s_sw[tid] = g_sw[r0 + tid];
    __syncthreads();

    float cs[RB8];
    {
        uint64_t acc[4];
        float bvj = bv[j];
        if (kh == 0) {
            #pragma unroll
            for (int i = 0; i < 4; i++) acc[i] = pack2(s_sw[2*i]*bvj, s_sw[2*i+1]*bvj);
        } else {
            #pragma unroll
            for (int i = 0; i < 4; i++) acc[i] = pack2(0.f, 0.f);
        }
        gemm8k(g_wvT, s_x, acc, j, k0);
        if (kh) {
            #pragma unroll
            for (int i = 0; i < 4; i++)
                unpack2(acc[i], s_red[j*RP + 2*i], s_red[j*RP + 2*i + 1]);
        }
        __syncthreads();
        if (!kh) {
            #pragma unroll
            for (int i = 0; i < 4; i++) {
                float lo, hi; unpack2(acc[i], lo, hi);
                cs[2*i]   = lo + s_red[j*RP + 2*i];
                cs[2*i+1] = hi + s_red[j*RP + 2*i + 1];
            }
            *(float4*)&s_x[j*XP]     = make_float4(cs[0], cs[1], cs[2], cs[3]);
            *(float4*)&s_x[j*XP + 4] = make_float4(cs[4], cs[5], cs[6], cs[7]);
        }
        __syncthreads();
    }

    {
        uint64_t acc[4];
        float b1j = (kh == 0) ? b1[j] : 0.f;
        #pragma unroll
        for (int i = 0; i < 4; i++) acc[i] = pack2(b1j, b1j);
        gemm8k(g_w1T, s_x, acc, j, k0);
        if (kh) {
            #pragma unroll
            for (int i = 0; i < 4; i++)
                unpack2(acc[i], s_red[j*RP + 2*i], s_red[j*RP + 2*i + 1]);
        }
        __syncthreads();
        if (!kh) {
            float hd[RB8];
            #pragma unroll
            for (int i = 0; i < 4; i++) {
                float lo, hi; unpack2(acc[i], lo, hi);
                hd[2*i]   = lo + s_red[j*RP + 2*i];
                hd[2*i+1] = hi + s_red[j*RP + 2*i + 1];
            }
            #pragma unroll
            for (int r = 0; r < RB8; r++) hd[r] = hd[r] > 0.f ? hd[r] : expm1f(hd[r]);
            *(float4*)&s_x[j*XP]     = make_float4(hd[0], hd[1], hd[2], hd[3]);
            *(float4*)&s_x[j*XP + 4] = make_float4(hd[4], hd[5], hd[6], hd[7]);
        }
        __syncthreads();
    }

    float y[RB8];
    {
        uint64_t acc[4];
        if (kh == 0) {
            float b2j = b2[j];
            #pragma unroll
            for (int i = 0; i < 4; i++) acc[i] = pack2(b2j + cs[2*i], b2j + cs[2*i+1]);
        } else {
            #pragma unroll
            for (int i = 0; i < 4; i++) acc[i] = pack2(0.f, 0.f);
        }
        gemm8k(g_w2T, s_x, acc, j, k0);
        if (kh) {
            #pragma unroll
            for (int i = 0; i < 4; i++)
                unpack2(acc[i], s_red[j*RP + 2*i], s_red[j*RP + 2*i + 1]);
        }
        __syncthreads();
        if (!kh) {
            #pragma unroll
            for (int i = 0; i < 4; i++) {
                float lo, hi; unpack2(acc[i], lo, hi);
                y[2*i]   = lo + s_red[j*RP + 2*i];
                y[2*i+1] = hi + s_red[j*RP + 2*i + 1];
            }
        }
        __syncthreads();
    }

    float* s_y = s_red;
    if (!kh) {
        #pragma unroll
        for (int r = 0; r < RB8; r++) s_y[r*H + j] = y[r];
    }
    __syncthreads();
    if (wid < 8) {
        int r = wid;
        float s = 0.f, q = 0.f;
        #pragma unroll
        for (int k = 0; k < 8; k++) {
            float vv = s_y[r*H + lane + 32*k];
            s += vv; q += vv*vv;
        }
        for (int off = 16; off; off >>= 1) {
            s += __shfl_down_sync(0xffffffffu, s, off);
            q += __shfl_down_sync(0xffffffffu, q, off);
        }
        if (lane == 0) {
            float mu = s * (1.f/H);
            float var = q * (1.f/H) - mu*mu;
            s_mu[r] = mu;
            s_rs[r] = rsqrtf(var + 1e-5f);
        }
    }
    __syncthreads();
    if (!kh) {
        float gj = gamma[j], bj = beta[j];
        #pragma unroll
        for (int r = 0; r < RB8; r++)
            out[(r0 + r)*H + j] = (y[r] - s_mu[r]) * s_rs[r] * gj + bj;
    }
}

extern "C" void kernel_launch(void* const* d_in, const int* in_sizes, int n_in,
                              void* d_out, int out_size) {
    const float* target_h = (const float*)d_in[0];
    const float* peer_h   = (const float*)d_in[1];
    const int*   peer_mask = (const int*)d_in[2];
    const float* wq = (const float*)d_in[3];
    const float* bq = (const float*)d_in[4];
    const float* wk = (const float*)d_in[5];
    const float* bk = (const float*)d_in[6];
    const float* wv = (const float*)d_in[7];
    const float* bv = (const float*)d_in[8];
    const float* w1 = (const float*)d_in[9];
    const float* b1 = (const float*)d_in[10];
    const float* w2 = (const float*)d_in[11];
    const float* b2 = (const float*)d_in[12];
    const float* gamma = (const float*)d_in[13];
    const float* beta  = (const float*)d_in[14];
    float* out = (float*)d_out;

    const int DOTS_SMEM = (TB*H + TB*NG*L + TB + NG + 8) * 4;
    cudaFuncSetAttribute(k_dots, cudaFuncAttributeMaxDynamicSharedMemorySize, DOTS_SMEM);

    k_prep<<<H + 3, 256>>>(wq, wk, bq, bk, wv, w1, w2);
    k_qtilde<<<BT/RB8, 512>>>(target_h);
    k_dots<<<B * (T/TB) * (N/NG), 256, DOTS_SMEM>>>(peer_h, peer_mask);
    k_topk<<<BT, 128>>>(peer_h);
    k_ffn<<<BT/RB8, 512>>>(bv, b1, b2, gamma, beta, out);
}

// round 17
// speedup vs baseline: 1.0925x; 1.0925x over previous
#include <cuda_runtime.h>
#include <math.h>
#include <stdint.h>

#define B 4
#define N 64
#define T 256
#define H 256
#define L 5
#define TOPK 8
#define BT (B*T)

#define RB8 8           // rows per block in GEMM kernels
#define XP 12           // transposed-activation row stride (16B-aligned)
#define RP 9            // reduction buffer stride (conflict-free)

// k_dots tiling
#define TB 64           // t-tile
#define NG 4            // peers per block
#define DOTS_THREADS 512

__constant__ int c_lags[L] = {1, 5, 10, 21, 30};

// -------- scratch (device globals: no allocation allowed) --------
__device__ float g_W[H*H];      // wq^T @ wk
__device__ float g_btil[H];     // bq @ wk
__device__ float g_v[H];        // wq^T @ bk
__device__ float g_c0;          // bq . bk
__device__ float g_wvT[H*H];
__device__ float g_w1T[H*H];
__device__ float g_w2T[H*H];
__device__ float g_Qt[BT*H];    // Q tilde
__device__ float g_c[BT];       // Q . bk per row
__device__ float g_lg[BT*N*L];  // full logits
__device__ float g_agg[BT*H];   // weighted sum of selected peer rows
__device__ float g_sw[BT];      // sum of weights

// ---- packed f32x2 helpers ----
__device__ __forceinline__ uint64_t pack2(float lo, float hi) {
    uint64_t r;
    asm("mov.b64 %0, {%1, %2};" : "=l"(r) : "f"(lo), "f"(hi));
    return r;
}
__device__ __forceinline__ void unpack2(uint64_t v, float& lo, float& hi) {
    asm("mov.b64 {%0, %1}, %2;" : "=f"(lo), "=f"(hi) : "l"(v));
}
__device__ __forceinline__ void ffma2(uint64_t& d, uint64_t a, uint64_t b) {
    asm("fma.rn.f32x2 %0, %1, %2, %0;" : "+l"(d) : "l"(a), "l"(b));
}

// ---- GEMM core: 8 rows, 128-long k-range starting at k0 (R14, measured).
__device__ __forceinline__ void gemm8k(const float* __restrict__ Wg,
                                       const float* __restrict__ XT,
                                       uint64_t* acc, int j, int k0) {
    float wb[2][8];
    #pragma unroll
    for (int p = 0; p < 2; p++)
        #pragma unroll
        for (int hh = 0; hh < 8; hh++) wb[p][hh] = Wg[(k0 + p*8 + hh)*H + j];

    ulonglong2 xs[2][2];
    {
        const ulonglong2* xp = (const ulonglong2*)(XT + (size_t)k0*XP);
        xs[0][0] = xp[0]; xs[0][1] = xp[1];
    }
    #pragma unroll 2
    for (int kt = 0; kt < 16; kt++) {
        int curb = kt & 1;
        float w[8];
        #pragma unroll
        for (int hh = 0; hh < 8; hh++) w[hh] = wb[curb][hh];
        if (kt + 2 < 16) {
            #pragma unroll
            for (int hh = 0; hh < 8; hh++)
                wb[curb][hh] = Wg[(k0 + (kt+2)*8 + hh)*H + j];
        }
        #pragma unroll
        for (int hh = 0; hh < 8; hh++) {
            int hrel = kt*8 + hh;
            int cur = hrel & 1, nxt = cur ^ 1;
            int hnrel = (hrel + 1) & 127;
            const ulonglong2* xp = (const ulonglong2*)(XT + (size_t)(k0 + hnrel)*XP);
            xs[nxt][0] = xp[0];
            xs[nxt][1] = xp[1];
            uint64_t w2 = pack2(w[hh], w[hh]);
            ffma2(acc[0], xs[cur][0].x, w2); ffma2(acc[1], xs[cur][0].y, w2);
            ffma2(acc[2], xs[cur][1].x, w2); ffma2(acc[3], xs[cur][1].y, w2);
        }
    }
}

// =============== prep: W = wq^T wk, biases folded, transposes ===============
__global__ void k_prep(const float* __restrict__ wq, const float* __restrict__ wk,
                       const float* __restrict__ bq, const float* __restrict__ bk,
                       const float* __restrict__ wv, const float* __restrict__ w1,
                       const float* __restrict__ w2) {
    int bidx = blockIdx.x;
    int j = threadIdx.x;
    if (bidx < H) {
        int h = bidx;
        __shared__ float s_wq[H];
        s_wq[j] = wq[j*H + h];
        __syncthreads();
        float acc = 0.f;
        #pragma unroll 4
        for (int m = 0; m < H; m++) acc += s_wq[m] * wk[m*H + j];
        g_W[h*H + j]   = acc;
        g_wvT[h*H + j] = wv[j*H + h];
        g_w1T[h*H + j] = w1[j*H + h];
        g_w2T[h*H + j] = w2[j*H + h];
    } else if (bidx == H) {
        float acc = 0.f;
        for (int m = 0; m < H; m++) acc += bq[m] * wk[m*H + j];
        g_btil[j] = acc;
    } else if (bidx == H + 1) {
        float acc = 0.f;
        for (int m = 0; m < H; m++) acc += wq[m*H + j] * bk[m];
        g_v[j] = acc;
    } else {
        if (j < 32) {
            float s = 0.f;
            for (int i = j; i < H; i += 32) s += bq[i] * bk[i];
            for (int off = 16; off; off >>= 1) s += __shfl_down_sync(0xffffffffu, s, off);
            if (j == 0) g_c0 = s;
        }
    }
}

// ========= Qtilde = target_h @ W + btil ; c = target_h . v + c0 (R14) =======
__global__ void __launch_bounds__(512) k_qtilde(const float* __restrict__ x) {
    __shared__ __align__(16) float s_x[H*XP];
    __shared__ float s_red[H*RP];
    __shared__ float s_part[16][4];
    int r0 = blockIdx.x * RB8;
    int tid = threadIdx.x;
    int j = tid & 255;
    int kh = tid >> 8;
    int k0 = kh << 7;
    int wid = tid >> 5, lane = tid & 31;

    float v4[4];
    #pragma unroll
    for (int r = 0; r < 4; r++) v4[r] = x[(r0 + kh*4 + r)*H + j];
    *(float4*)&s_x[j*XP + kh*4] = make_float4(v4[0], v4[1], v4[2], v4[3]);

    float gv = g_v[j];
    #pragma unroll
    for (int r = 0; r < 4; r++) {
        float s = v4[r] * gv;
        for (int off = 16; off; off >>= 1) s += __shfl_down_sync(0xffffffffu, s, off);
        if (lane == 0) s_part[wid][r] = s;
    }
    __syncthreads();
    if (tid < RB8) {
        int src = tid >> 2, rs = tid & 3;
        float s = g_c0;
        #pragma unroll
        for (int w = 0; w < 8; w++) s += s_part[src*8 + w][rs];
        g_c[r0 + tid] = s;
    }

    uint64_t acc[4];
    float bt = (kh == 0) ? g_btil[j] : 0.f;
    #pragma unroll
    for (int i = 0; i < 4; i++) acc[i] = pack2(bt, bt);
    gemm8k(g_W, s_x, acc, j, k0);

    if (kh) {
        #pragma unroll
        for (int i = 0; i < 4; i++) {
            float lo, hi; unpack2(acc[i], lo, hi);
            s_red[j*RP + 2*i] = lo; s_red[j*RP + 2*i + 1] = hi;
        }
    }
    __syncthreads();
    if (!kh) {
        #pragma unroll
        for (int i = 0; i < 4; i++) {
            float lo, hi; unpack2(acc[i], lo, hi);
            g_Qt[(r0 + 2*i    )*H + j] = lo + s_red[j*RP + 2*i];
            g_Qt[(r0 + 2*i + 1)*H + j] = hi + s_red[j*RP + 2*i + 1];
        }
    }
}

// ===== k_dots: logits for (b, 64-t tile, 4-peer group). 512 threads (16
// warps). Each peer row loaded ONCE, dotted against up to 5 staged Q rows.
// Row prefetch issued before the interleaved shfl-reduction chains.
__global__ void __launch_bounds__(DOTS_THREADS) k_dots(
                       const float* __restrict__ peer,
                       const int* __restrict__ mask) {
    extern __shared__ float sm[];
    float* s_q  = sm;                   // [TB][H] = 65536 B
    float* s_lg = sm + TB*H;            // [TB][NG][L]
    float* s_c  = s_lg + TB*NG*L;       // [TB]
    int*   s_mi = (int*)(s_c + TB);     // [NG]

    int bid = blockIdx.x;
    int ng = bid & 15;                  // 16 n-groups of 4
    int tt = (bid >> 4) & 3;            // 4 t-tiles of 64
    int b  = bid >> 6;
    int t0 = tt * TB;
    int n0 = ng * NG;
    int tid = threadIdx.x;              // 512
    int wid = tid >> 5, lane = tid & 31;

    {
        const float4* src = (const float4*)&g_Qt[(b*T + t0)*H];
        float4* dst = (float4*)s_q;
        for (int i = tid; i < TB*H/4; i += DOTS_THREADS) dst[i] = src[i];
        for (int i = tid; i < TB*NG*L; i += DOTS_THREADS) s_lg[i] = -INFINITY;
        if (tid < TB) s_c[tid] = g_c[b*T + t0 + tid];
        if (tid < NG) s_mi[tid] = mask[b*N + n0 + tid];
    }
    __syncthreads();

    int tp_lo = t0 - 30; if (tp_lo < 0) tp_lo = 0;
    int tp_hi = t0 + TB - 2;

    for (int nl = 0; nl < NG; nl++) {
        if (!s_mi[nl]) continue;
        const float4* base = (const float4*)(peer + ((size_t)((b*N + n0 + nl)*T)) * H);
        int tp = tp_lo + wid;           // 16 warps stride tp by 16
        if (tp > tp_hi) continue;
        float4 c0 = base[tp*64 + lane];
        float4 c1 = base[tp*64 + 32 + lane];
        while (tp <= tp_hi) {
            int tpn = tp + 16;
            float4 p0, p1;
            if (tpn <= tp_hi) {         // prefetch next row before the shfl chain
                p0 = base[tpn*64 + lane];
                p1 = base[tpn*64 + 32 + lane];
            }
            float s[L]; int tl[L];
            #pragma unroll
            for (int l = 0; l < L; l++) {
                tl[l] = tp + c_lags[l] - t0;
                s[l] = 0.f;
                if ((unsigned)tl[l] < TB) {
                    const float4* q4 = (const float4*)&s_q[tl[l]*H];
                    float4 q0 = q4[lane];
                    float4 q1 = q4[lane + 32];
                    s[l] = c0.x*q0.x + c0.y*q0.y + c0.z*q0.z + c0.w*q0.w
                         + c1.x*q1.x + c1.y*q1.y + c1.z*q1.z + c1.w*q1.w;
                }
            }
            #pragma unroll
            for (int off = 16; off; off >>= 1) {
                #pragma unroll
                for (int l = 0; l < L; l++)
                    s[l] += __shfl_down_sync(0xffffffffu, s[l], off);
            }
            if (lane == 0) {
                #pragma unroll
                for (int l = 0; l < L; l++)
                    if ((unsigned)tl[l] < TB)
                        s_lg[(tl[l]*NG + nl)*L + l] = (s[l] + s_c[tl[l]]) * 0.0625f;
            }
            tp = tpn; c0 = p0; c1 = p1;
        }
    }
    __syncthreads();

    // flush: g_lg[(b*T+t)*(N*L) + n0*L + (nl*L+l)]
    for (int i = tid; i < TB*NG*L; i += DOTS_THREADS) {
        int trow = i / (NG*L);
        int rem = i - trow*(NG*L);
        g_lg[(size_t)(b*T + t0 + trow)*(N*L) + n0*L + rem] = s_lg[i];
    }
}

// ===== k_topk (R7, measured 11.0us): top-8 over 320, softmax, aggregate =====
__global__ void k_topk(const float* __restrict__ peer) {
    __shared__ float s_l[N*L];
    __shared__ float swt[TOPK];
    __shared__ int   sidx[TOPK];
    int bt = blockIdx.x;
    int b = bt >> 8;
    int t = bt & 255;
    int tid = threadIdx.x;          // 128 threads
    int wid = tid >> 5, lane = tid & 31;

    for (int i = tid; i < N*L; i += 128) s_l[i] = g_lg[(size_t)bt*(N*L) + i];
    __syncthreads();

    if (wid == 0) {
        float vals[TOPK];
        for (int k = 0; k < TOPK; k++) {
            float bv = -INFINITY; int bi = 0x7fffffff;
            for (int i = lane; i < N*L; i += 32) {
                float v = s_l[i];
                if (v > bv || (v == bv && i < bi)) { bv = v; bi = i; }
            }
            for (int off = 16; off; off >>= 1) {
                float ov = __shfl_down_sync(0xffffffffu, bv, off);
                int   oi = __shfl_down_sync(0xffffffffu, bi, off);
                if (ov > bv || (ov == bv && oi < bi)) { bv = ov; bi = oi; }
            }
            bi = __shfl_sync(0xffffffffu, bi, 0);
            bv = __shfl_sync(0xffffffffu, bv, 0);
            if (lane == 0) { sidx[k] = bi; vals[k] = bv; s_l[bi] = -INFINITY; }
            __syncwarp();
        }
        if (lane == 0) {
            float m = -INFINITY;
            bool allinf = true;
            float safe[TOPK];
            #pragma unroll
            for (int k = 0; k < TOPK; k++) {
                bool ii = isinf(vals[k]);
                allinf = allinf && ii;
                safe[k] = ii ? -1e9f : vals[k];
                if (safe[k] > m) m = safe[k];
            }
            float sw_ = 0.f;
            if (allinf) {
                #pragma unroll
                for (int k = 0; k < TOPK; k++) swt[k] = 0.f;
            } else {
                float e[TOPK]; float tot = 0.f;
                #pragma unroll
                for (int k = 0; k < TOPK; k++) { e[k] = expf(safe[k] - m); tot += e[k]; }
                #pragma unroll
                for (int k = 0; k < TOPK; k++) { float w = e[k] / tot; swt[k] = w; sw_ += w; }
            }
            g_sw[bt] = sw_;
        }
    }
    __syncthreads();

    float acc0 = 0.f, acc1 = 0.f;
    #pragma unroll
    for (int k = 0; k < TOPK; k++) {
        float w = swt[k];
        if (w != 0.f) {
            int d = sidx[k];
            int n = d / L, l = d - n*L;
            int tp = t - c_lags[l];
            const float* row = peer + ((size_t)((b*N + n)*T + tp)) * H;
            acc0 += w * row[tid];
            acc1 += w * row[tid + 128];
        }
    }
    g_agg[bt*H + tid]       = acc0;
    g_agg[bt*H + tid + 128] = acc1;
}

// ===== cs_y = agg@wv^T + sw*bv ; FFN(elu) ; residual ; LayerNorm (R14) ======
__global__ void __launch_bounds__(512) k_ffn(
                      const float* __restrict__ bv, const float* __restrict__ b1,
                      const float* __restrict__ b2, const float* __restrict__ gamma,
                      const float* __restrict__ beta, float* __restrict__ out) {
    __shared__ __align__(16) float s_x[H*XP];
    __shared__ float s_red[H*RP];
    __shared__ float s_sw[RB8];
    __shared__ float s_mu[RB8], s_rs[RB8];

    int r0 = blockIdx.x * RB8;
    int tid = threadIdx.x;
    int j = tid & 255;
    int kh = tid >> 8;
    int k0 = kh << 7;
    int wid = tid >> 5, lane = tid & 31;

    {
        float v4[4];
        #pragma unroll
        for (int r = 0; r < 4; r++) v4[r] = g_agg[(r0 + kh*4 + r)*H + j];
        *(float4*)&s_x[j*XP + kh*4] = make_float4(v4[0], v4[1], v4[2], v4[3]);
    }
    if (tid < RB8) s_sw[tid] = g_sw[r0 + tid];
    __syncthreads();

    float cs[RB8];
    {
        uint64_t acc[4];
        float bvj = bv[j];
        if (kh == 0) {
            #pragma unroll
            for (int i = 0; i < 4; i++) acc[i] = pack2(s_sw[2*i]*bvj, s_sw[2*i+1]*bvj);
        } else {
            #pragma unroll
            for (int i = 0; i < 4; i++) acc[i] = pack2(0.f, 0.f);
        }
        gemm8k(g_wvT, s_x, acc, j, k0);
        if (kh) {
            #pragma unroll
            for (int i = 0; i < 4; i++)
                unpack2(acc[i], s_red[j*RP + 2*i], s_red[j*RP + 2*i + 1]);
        }
        __syncthreads();
        if (!kh) {
            #pragma unroll
            for (int i = 0; i < 4; i++) {
                float lo, hi; unpack2(acc[i], lo, hi);
                cs[2*i]   = lo + s_red[j*RP + 2*i];
                cs[2*i+1] = hi + s_red[j*RP + 2*i + 1];
            }
            *(float4*)&s_x[j*XP]     = make_float4(cs[0], cs[1], cs[2], cs[3]);
            *(float4*)&s_x[j*XP + 4] = make_float4(cs[4], cs[5], cs[6], cs[7]);
        }
        __syncthreads();
    }

    {
        uint64_t acc[4];
        float b1j = (kh == 0) ? b1[j] : 0.f;
        #pragma unroll
        for (int i = 0; i < 4; i++) acc[i] = pack2(b1j, b1j);
        gemm8k(g_w1T, s_x, acc, j, k0);
        if (kh) {
            #pragma unroll
            for (int i = 0; i < 4; i++)
                unpack2(acc[i], s_red[j*RP + 2*i], s_red[j*RP + 2*i + 1]);
        }
        __syncthreads();
        if (!kh) {
            float hd[RB8];
            #pragma unroll
            for (int i = 0; i < 4; i++) {
                float lo, hi; unpack2(acc[i], lo, hi);
                hd[2*i]   = lo + s_red[j*RP + 2*i];
                hd[2*i+1] = hi + s_red[j*RP + 2*i + 1];
            }
            #pragma unroll
            for (int r = 0; r < RB8; r++) hd[r] = hd[r] > 0.f ? hd[r] : expm1f(hd[r]);
            *(float4*)&s_x[j*XP]     = make_float4(hd[0], hd[1], hd[2], hd[3]);
            *(float4*)&s_x[j*XP + 4] = make_float4(hd[4], hd[5], hd[6], hd[7]);
        }
        __syncthreads();
    }

    float y[RB8];
    {
        uint64_t acc[4];
        if (kh == 0) {
            float b2j = b2[j];
            #pragma unroll
            for (int i = 0; i < 4; i++) acc[i] = pack2(b2j + cs[2*i], b2j + cs[2*i+1]);
        } else {
            #pragma unroll
            for (int i = 0; i < 4; i++) acc[i] = pack2(0.f, 0.f);
        }
        gemm8k(g_w2T, s_x, acc, j, k0);
        if (kh) {
            #pragma unroll
            for (int i = 0; i < 4; i++)
                unpack2(acc[i], s_red[j*RP + 2*i], s_red[j*RP + 2*i + 1]);
        }
        __syncthreads();
        if (!kh) {
            #pragma unroll
            for (int i = 0; i < 4; i++) {
                float lo, hi; unpack2(acc[i], lo, hi);
                y[2*i]   = lo + s_red[j*RP + 2*i];
                y[2*i+1] = hi + s_red[j*RP + 2*i + 1];
            }
        }
        __syncthreads();
    }

    float* s_y = s_red;
    if (!kh) {
        #pragma unroll
        for (int r = 0; r < RB8; r++) s_y[r*H + j] = y[r];
    }
    __syncthreads();
    if (wid < 8) {
        int r = wid;
        float s = 0.f, q = 0.f;
        #pragma unroll
        for (int k = 0; k < 8; k++) {
            float vv = s_y[r*H + lane + 32*k];
            s += vv; q += vv*vv;
        }
        for (int off = 16; off; off >>= 1) {
            s += __shfl_down_sync(0xffffffffu, s, off);
            q += __shfl_down_sync(0xffffffffu, q, off);
        }
        if (lane == 0) {
            float mu = s * (1.f/H);
            float var = q * (1.f/H) - mu*mu;
            s_mu[r] = mu;
            s_rs[r] = rsqrtf(var + 1e-5f);
        }
    }
    __syncthreads();
    if (!kh) {
        float gj = gamma[j], bj = beta[j];
        #pragma unroll
        for (int r = 0; r < RB8; r++)
            out[(r0 + r)*H + j] = (y[r] - s_mu[r]) * s_rs[r] * gj + bj;
    }
}

extern "C" void kernel_launch(void* const* d_in, const int* in_sizes, int n_in,
                              void* d_out, int out_size) {
    const float* target_h = (const float*)d_in[0];
    const float* peer_h   = (const float*)d_in[1];
    const int*   peer_mask = (const int*)d_in[2];
    const float* wq = (const float*)d_in[3];
    const float* bq = (const float*)d_in[4];
    const float* wk = (const float*)d_in[5];
    const float* bk = (const float*)d_in[6];
    const float* wv = (const float*)d_in[7];
    const float* bv = (const float*)d_in[8];
    const float* w1 = (const float*)d_in[9];
    const float* b1 = (const float*)d_in[10];
    const float* w2 = (const float*)d_in[11];
    const float* b2 = (const float*)d_in[12];
    const float* gamma = (const float*)d_in[13];
    const float* beta  = (const float*)d_in[14];
    float* out = (float*)d_out;

    const int DOTS_SMEM = (TB*H + TB*NG*L + TB + NG + 8) * 4;
    cudaFuncSetAttribute(k_dots, cudaFuncAttributeMaxDynamicSharedMemorySize, DOTS_SMEM);

    k_prep<<<H + 3, 256>>>(wq, wk, bq, bk, wv, w1, w2);
    k_qtilde<<<BT/RB8, 512>>>(target_h);
    k_dots<<<B * (T/TB) * (N/NG), DOTS_THREADS, DOTS_SMEM>>>(peer_h, peer_mask);
    k_topk<<<BT, 128>>>(peer_h);
    k_ffn<<<BT/RB8, 512>>>(bv, b1, b2, gamma, beta, out);
}